// round 15
// baseline (speedup 1.0000x reference)
#include <cuda_runtime.h>
#include <cstdint>
#include <math.h>

#define B_SZ  32
#define T_LEN 2048
#define I_DIM 128
#define H_DIM 256
#define N_TOK (B_SZ * T_LEN)   // 65536

// Scratch (device globals: allocation-free rule)
__device__ float g_xB[(size_t)N_TOK * H_DIM];   // 64 MB
__device__ float g_hs[(size_t)N_TOK * H_DIM];   // 64 MB

// ---------------------------------------------------------------------------
// helpers
// ---------------------------------------------------------------------------
__device__ __forceinline__ uint32_t smem_u32(const void* p) {
    uint32_t a;
    asm("{ .reg .u64 t; cvta.to.shared.u64 t, %1; cvt.u32.u64 %0, t; }"
        : "=r"(a) : "l"(p));
    return a;
}
__device__ __forceinline__ void mbar_wait(uint32_t mbar, uint32_t parity) {
    asm volatile(
        "{\n\t.reg .pred P;\n\t"
        "WAITLOOP_%=:\n\t"
        "mbarrier.try_wait.parity.acquire.cta.shared::cta.b64 P, [%0], %1, 0x989680;\n\t"
        "@P bra.uni WAITDONE_%=;\n\t"
        "bra.uni WAITLOOP_%=;\n\t"
        "WAITDONE_%=:\n\t}"
        :: "r"(mbar), "r"(parity) : "memory");
}
__device__ __forceinline__ float tanh_fast(float x) {
    float y;
    asm("tanh.approx.f32 %0, %1;" : "=f"(y) : "f"(x));
    return y;
}

// ---------------------------------------------------------------------------
// fp32 tiled GEMM (scalar FFMA): Y[M,N] = X[M,K] @ W[K,N]
// BM=128, BN=64, BK=16, 256 threads, 8x4 micro-tile per thread.
// ---------------------------------------------------------------------------
__global__ void __launch_bounds__(256) gemm_kernel(const float* __restrict__ X,
                                                   const float* __restrict__ W,
                                                   float* __restrict__ Y,
                                                   int M, int K, int N) {
    __shared__ float Xs[16][128];
    __shared__ float Ws[16][64];

    const int tid = threadIdx.x;
    const int m0 = blockIdx.x * 128;
    const int n0 = blockIdx.y * 64;
    const int tx = tid & 15;
    const int ty = tid >> 4;

    float acc[8][4];
#pragma unroll
    for (int r = 0; r < 8; r++)
#pragma unroll
        for (int cc = 0; cc < 4; cc++) acc[r][cc] = 0.f;

    const int lrow  = tid >> 1;
    const int lpart = (tid & 1) * 8;

    for (int kt = 0; kt < K; kt += 16) {
        const float* xp = X + (size_t)(m0 + lrow) * K + kt + lpart;
        float4 v0 = *(const float4*)(xp);
        float4 v1 = *(const float4*)(xp + 4);
        Xs[lpart + 0][lrow] = v0.x;
        Xs[lpart + 1][lrow] = v0.y;
        Xs[lpart + 2][lrow] = v0.z;
        Xs[lpart + 3][lrow] = v0.w;
        Xs[lpart + 4][lrow] = v1.x;
        Xs[lpart + 5][lrow] = v1.y;
        Xs[lpart + 6][lrow] = v1.z;
        Xs[lpart + 7][lrow] = v1.w;
        {
            const int wk = tid >> 4;
            const int wn = (tid & 15) * 4;
            float4 wv = *(const float4*)(W + (size_t)(kt + wk) * N + n0 + wn);
            *(float4*)&Ws[wk][wn] = wv;
        }
        __syncthreads();

#pragma unroll
        for (int k = 0; k < 16; k++) {
            float4 xa = *(const float4*)&Xs[k][ty * 8];
            float4 xb = *(const float4*)&Xs[k][ty * 8 + 4];
            float4 wv = *(const float4*)&Ws[k][tx * 4];
            float xr[8] = {xa.x, xa.y, xa.z, xa.w, xb.x, xb.y, xb.z, xb.w};
            float wr[4] = {wv.x, wv.y, wv.z, wv.w};
#pragma unroll
            for (int r = 0; r < 8; r++)
#pragma unroll
                for (int cc = 0; cc < 4; cc++)
                    acc[r][cc] = fmaf(xr[r], wr[cc], acc[r][cc]);
        }
        __syncthreads();
    }

#pragma unroll
    for (int r = 0; r < 8; r++) {
        float4 o = make_float4(acc[r][0], acc[r][1], acc[r][2], acc[r][3]);
        *(float4*)&Y[(size_t)(m0 + ty * 8 + r) * N + n0 + tx * 4] = o;
    }
}

// ---------------------------------------------------------------------------
// Scan kernel: 4-CTA cluster per PAIR of batches (16 clusters, 64 CTAs,
// 256 threads each). Both batches share the SAME A (registers reused).
// CTA rank owns cols [rank*64, rank*64+64). Thread (g = tid>>2, c = tid&3):
// col = rank*64 + g, k-window [c*64, c*64+64).
// Per step: phase A (wait/dot/reduce/send batch0) then phase B (batch1).
// Batch0's DSMEM transit is hidden under phase B's compute and vice versa.
// h TRIPLE-buffered per batch (6 buffers, 6 mbarriers).
// Skew 64+4 floats per block: the 4 c-window reads per warp instruction land
// on banks {0,4,8,12} -> 1 phase per LDS.128.
// ---------------------------------------------------------------------------
#define HBLK 68
#define HB   (4 * HBLK)               // 272 floats per buffer
#define TXB  (3 * 64 * 4)             // 768 B incoming per batch per step

__global__ void __launch_bounds__(256, 1) __cluster_dims__(4, 1, 1)
scan_kernel(const float* __restrict__ A) {
    __shared__ __align__(16) float hbuf[6][HB];          // [batch*3+buf]
    __shared__ __align__(8) unsigned long long bars[6];

    const int tid = threadIdx.x;
    uint32_t rank;
    asm("mov.u32 %0, %%cluster_ctarank;" : "=r"(rank));
    const int cid = blockIdx.x >> 2;     // cluster id 0..15
    const int b0  = 2 * cid;
    const int b1  = 2 * cid + 1;
    const int g   = tid >> 2;            // 0..63
    const int c   = tid & 3;             // 0..3
    const int col = (int)rank * 64 + g;
    const int k0  = c * 64;

    // A slice fully into registers (shared by both batches)
    float a[64];
    {
        const float* Ac = A + (size_t)k0 * H_DIM + col;
#pragma unroll
        for (int k = 0; k < 64; k++) a[k] = Ac[(size_t)k * H_DIM];
    }

    const uint32_t bar0 = smem_u32(&bars[0]);
    if (tid == 0) {
#pragma unroll
        for (int i = 0; i < 6; i++)
            asm volatile("mbarrier.init.shared.b64 [%0], 1;"
                         :: "r"(bar0 + 8u * i) : "memory");
    }
    for (int i = tid; i < 6 * HB; i += 256) ((float*)hbuf)[i] = 0.f;
    __syncthreads();
    asm volatile("barrier.cluster.arrive.aligned;" ::: "memory");
    asm volatile("barrier.cluster.wait.aligned;" ::: "memory");

    // my column's slot index (same in every CTA's buffers)
    const int wr_idx = (int)rank * HBLK + g;
    uint32_t p_slot0[3], p_bar0[3];      // peer base addrs (buffer 0)
    {
        uint32_t my_slot0 = smem_u32(&hbuf[0][wr_idx]);
#pragma unroll
        for (int p = 0; p < 3; p++) {
            uint32_t pr = (rank + 1u + p) & 3u;
            asm("mapa.shared::cluster.u32 %0, %1, %2;" : "=r"(p_slot0[p]) : "r"(my_slot0), "r"(pr));
            asm("mapa.shared::cluster.u32 %0, %1, %2;" : "=r"(p_bar0[p])  : "r"(bar0), "r"(pr));
        }
    }

    const float* xB0 = g_xB + (size_t)b0 * T_LEN * H_DIM;
    const float* xB1 = g_xB + (size_t)b1 * T_LEN * H_DIM;
    float*       hs0 = g_hs + (size_t)b0 * T_LEN * H_DIM;
    float*       hs1 = g_hs + (size_t)b1 * T_LEN * H_DIM;
    const int rd_off = c * HBLK;

    float xb0_cur = (c == 0) ? xB0[col] : 0.f;
    float xb1_cur = (c == 0) ? xB1[col] : 0.f;

    int rb = 0;                // s % 3
    for (int s = 0; s < T_LEN; s++) {
        const int wb = (rb == 2) ? 0 : rb + 1;

        // arm both batches' bar[wb] for this step's incoming 768 B each
        if (tid == 0 && s + 1 < T_LEN) {
            asm volatile("mbarrier.arrive.expect_tx.shared.b64 _, [%0], %1;"
                         :: "r"(bar0 + 8u * wb), "r"((uint32_t)TXB) : "memory");
            asm volatile("mbarrier.arrive.expect_tx.shared.b64 _, [%0], %1;"
                         :: "r"(bar0 + 8u * (3 + wb)), "r"((uint32_t)TXB) : "memory");
        }

        float xb0_nxt = xb0_cur, xb1_nxt = xb1_cur;
        if (c == 0 && s + 1 < T_LEN) {
            xb0_nxt = xB0[(size_t)(s + 1) * H_DIM + col];
            xb1_nxt = xB1[(size_t)(s + 1) * H_DIM + col];
        }
        const uint32_t wpar = (uint32_t)(((s - 1) / 3) & 1);

        // ================= phase A: batch b0 =================
        if (s > 0) mbar_wait(bar0 + 8u * rb, wpar);
        {
            const float4* hp = (const float4*)(&hbuf[rb][rd_off]);
            float acc0 = 0.f, acc1 = 0.f;
#pragma unroll
            for (int q = 0; q < 16; q++) {
                float4 hv = hp[q];
                acc0 = fmaf(hv.x, a[4 * q + 0], acc0);
                acc1 = fmaf(hv.y, a[4 * q + 1], acc1);
                acc0 = fmaf(hv.z, a[4 * q + 2], acc0);
                acc1 = fmaf(hv.w, a[4 * q + 3], acc1);
            }
            float sum = acc0 + acc1;
            sum += __shfl_xor_sync(0xffffffffu, sum, 1);
            sum += __shfl_xor_sync(0xffffffffu, sum, 2);
            if (c == 0) {
                float y = tanh_fast(sum + xb0_cur);
                hbuf[wb][wr_idx] = y;
                if (s + 1 < T_LEN) {
                    uint32_t yb = __float_as_uint(y);
                    uint32_t soff = (uint32_t)(wb * HB * 4);
                    uint32_t boff = 8u * (uint32_t)wb;
#pragma unroll
                    for (int p = 0; p < 3; p++)
                        asm volatile(
                            "st.async.weak.shared::cluster.mbarrier::complete_tx::bytes.b32 "
                            "[%0], %1, [%2];"
                            :: "r"(p_slot0[p] + soff), "r"(yb), "r"(p_bar0[p] + boff)
                            : "memory");
                }
                hs0[(size_t)s * H_DIM + col] = y;
                xb0_cur = xb0_nxt;
            }
        }

        // ================= phase B: batch b1 =================
        if (s > 0) mbar_wait(bar0 + 8u * (3 + rb), wpar);
        {
            const float4* hp = (const float4*)(&hbuf[3 + rb][rd_off]);
            float acc0 = 0.f, acc1 = 0.f;
#pragma unroll
            for (int q = 0; q < 16; q++) {
                float4 hv = hp[q];
                acc0 = fmaf(hv.x, a[4 * q + 0], acc0);
                acc1 = fmaf(hv.y, a[4 * q + 1], acc1);
                acc0 = fmaf(hv.z, a[4 * q + 2], acc0);
                acc1 = fmaf(hv.w, a[4 * q + 3], acc1);
            }
            float sum = acc0 + acc1;
            sum += __shfl_xor_sync(0xffffffffu, sum, 1);
            sum += __shfl_xor_sync(0xffffffffu, sum, 2);
            if (c == 0) {
                float y = tanh_fast(sum + xb1_cur);
                hbuf[3 + wb][wr_idx] = y;
                if (s + 1 < T_LEN) {
                    uint32_t yb = __float_as_uint(y);
                    uint32_t soff = (uint32_t)((3 + wb) * HB * 4);
                    uint32_t boff = 8u * (uint32_t)(3 + wb);
#pragma unroll
                    for (int p = 0; p < 3; p++)
                        asm volatile(
                            "st.async.weak.shared::cluster.mbarrier::complete_tx::bytes.b32 "
                            "[%0], %1, [%2];"
                            :: "r"(p_slot0[p] + soff), "r"(yb), "r"(p_bar0[p] + boff)
                            : "memory");
                }
                hs1[(size_t)s * H_DIM + col] = y;
                xb1_cur = xb1_nxt;
            }
        }

        __syncthreads();   // local writes to hbuf[wb]/hbuf[3+wb] visible
        rb = wb;
    }

    // no CTA may exit while peer st.async traffic could be in flight
    asm volatile("barrier.cluster.arrive.aligned;" ::: "memory");
    asm volatile("barrier.cluster.wait.aligned;" ::: "memory");
}

// ---------------------------------------------------------------------------
extern "C" void kernel_launch(void* const* d_in, const int* in_sizes, int n_in,
                              void* d_out, int out_size) {
    const float* x  = (const float*)d_in[0];   // [32,2048,128]
    const float* A  = (const float*)d_in[1];   // [256,256]
    const float* Bm = (const float*)d_in[2];   // [128,256]
    const float* C  = (const float*)d_in[3];   // [256,256]
    float* out = (float*)d_out;                // [32,2048,256]

    float* xBp = nullptr;
    float* hsp = nullptr;
    cudaGetSymbolAddress((void**)&xBp, g_xB);
    cudaGetSymbolAddress((void**)&hsp, g_hs);

    // 1) xB = x @ Bm : [65536,128] @ [128,256]
    gemm_kernel<<<dim3(N_TOK / 128, H_DIM / 64), 256>>>(x, Bm, xBp, N_TOK, I_DIM, H_DIM);
    // 2) sequential scan: 4-CTA cluster per batch-pair, phase-interleaved
    scan_kernel<<<(B_SZ / 2) * 4, 256>>>(A);
    // 3) out = hs @ C : [65536,256] @ [256,256]
    gemm_kernel<<<dim3(N_TOK / 128, H_DIM / 64), 256>>>(hsp, C, out, N_TOK, H_DIM, H_DIM);
}